// round 13
// baseline (speedup 1.0000x reference)
#include <cuda_runtime.h>
#include <cstdint>

// Problem dims (fixed: T=2048, B=32, D=512)
#define T_DIM 2048
#define B_DIM 32
#define D_DIM 512
#define M_DIM (T_DIM * B_DIM)   // 65536 GEMM rows
#define BD    (B_DIM * D_DIM)   // 16384 scan lanes

// Scratch: Y = x @ W^T + b (fp32, 134 MB)
__device__ float g_Y[(size_t)M_DIM * D_DIM];

// ---------------------------------------------------------------------------
// SGEMM: Y[m,e] = sum_k X[m,k]*W[e,k] + bias[e]
// CONSTRAINT: per output, fp32 fmaf chain with k strictly ascending 0..511
// (bit-matches the reference rounding; any reassociation flips spikes).
// Round-12 structure (CTA 128x128, 8 warps, BKT=16 double buffer, occ 2).
// ONE change: f32x2 pairs along M (thread tile 16m x 4n). A m-pairs are
// natural ulonglong2 LDS reads (zero pack MOVs); only 4 B dup-packs per k.
// Issues/warp-k: 44 -> 41, FFMA2 density 73% -> 78%.
// ---------------------------------------------------------------------------
#define BMT 128
#define BNT 128
#define BKT 16
#define NKT (D_DIM / BKT)   // 32

typedef unsigned long long u64t;

__device__ __forceinline__ void ffma2(u64t& d, u64t a, u64t b) {
    asm("fma.rn.f32x2 %0, %1, %2, %0;" : "+l"(d) : "l"(a), "l"(b));
}
__device__ __forceinline__ u64t pack_dup(float x) {
    u64t r;
    asm("mov.b64 %0, {%1, %1};" : "=l"(r) : "f"(x));
    return r;
}
__device__ __forceinline__ void unpack2(u64t p, float& lo, float& hi) {
    asm("mov.b64 {%0, %1}, %2;" : "=f"(lo), "=f"(hi) : "l"(p));
}

__global__ __launch_bounds__(256, 2)
void sgemm_kernel(const float* __restrict__ X, const float* __restrict__ Wm,
                  const float* __restrict__ bias) {
    __shared__ __align__(16) float As[2][BKT][BMT];   // 16 KB
    __shared__ __align__(16) float Bs[2][BKT][BNT];   // 16 KB

    const int tid = threadIdx.x;
    const int bn  = blockIdx.x * BNT;   // 4 values, inner -> X L2 reuse
    const int bm  = blockIdx.y * BMT;   // 512 values

    // 8 warps = 4(m) x 2(n); warp tile 32m x 64n; thread tile 16m x 4n
    const int wid    = tid >> 5;
    const int lane   = tid & 31;
    const int warp_m = wid >> 1;              // 0..3
    const int warp_n = wid & 1;               // 0..1
    const int lm     = lane >> 4;             // 0..1
    const int ln     = lane & 15;             // 0..15
    const int tm0    = warp_m * 32 + lm * 16; // 16 consecutive m rows
    const int tn0    = warp_n * 64 + ln * 4;  // 4 consecutive n cols

    // gmem load mapping: 4 threads per row (one float4 of k each), 2 sweeps
    const int gr = tid >> 2;                  // 0..63
    const int gk = (tid & 3) << 2;            // 0,4,8,12

    const float* Xg = X  + (size_t)(bm + gr) * D_DIM + gk;
    const float* Wg = Wm + (size_t)(bn + gr) * D_DIM + gk;

    // acc[p][j]: m-pair p -> rows tm0+2p, tm0+2p+1 (lo/hi lanes); col tn0+j
    u64t acc[8][4];
#pragma unroll
    for (int p = 0; p < 8; p++)
#pragma unroll
        for (int j = 0; j < 4; j++) acc[p][j] = 0ull;

    // prologue: chunk 0 -> buffer 0
    {
        float4 a0 = *(const float4*)(Xg);
        float4 a1 = *(const float4*)(Xg + (size_t)64 * D_DIM);
        float4 b0 = *(const float4*)(Wg);
        float4 b1 = *(const float4*)(Wg + (size_t)64 * D_DIM);
#pragma unroll
        for (int c = 0; c < 4; c++) {
            As[0][gk + c][gr]      = ((const float*)&a0)[c];
            As[0][gk + c][gr + 64] = ((const float*)&a1)[c];
            Bs[0][gk + c][gr]      = ((const float*)&b0)[c];
            Bs[0][gk + c][gr + 64] = ((const float*)&b1)[c];
        }
    }
    __syncthreads();

    for (int kt = 1; kt <= NKT; kt++) {
        const int buf = (kt - 1) & 1;

        float4 na0, na1, nb0, nb1;
        if (kt < NKT) {
            const int k0 = kt * BKT;
            na0 = *(const float4*)(Xg + k0);
            na1 = *(const float4*)(Xg + k0 + (size_t)64 * D_DIM);
            nb0 = *(const float4*)(Wg + k0);
            nb1 = *(const float4*)(Wg + k0 + (size_t)64 * D_DIM);
        }

#pragma unroll
        for (int k = 0; k < BKT; k++) {
            // A: 4 LDS.128 of 16 contiguous m floats -> 8 natural f32x2 pairs
            u64t ap[8];
#pragma unroll
            for (int q = 0; q < 4; q++) {
                ulonglong2 a2 = *(const ulonglong2*)&As[buf][k][tm0 + q * 4];
                ap[q * 2 + 0] = a2.x;
                ap[q * 2 + 1] = a2.y;
            }

            // B: 1 LDS.128 (16 lanes x 16B = 256B contiguous) + 4 dup packs
            float4 bv = *(const float4*)&Bs[buf][k][tn0];
            u64t bd[4];
            bd[0] = pack_dup(bv.x); bd[1] = pack_dup(bv.y);
            bd[2] = pack_dup(bv.z); bd[3] = pack_dup(bv.w);

#pragma unroll
            for (int p = 0; p < 8; p++)
#pragma unroll
                for (int j = 0; j < 4; j++)
                    ffma2(acc[p][j], ap[p], bd[j]);
        }

        if (kt < NKT) {
            const int nbuf = kt & 1;
#pragma unroll
            for (int c = 0; c < 4; c++) {
                As[nbuf][gk + c][gr]      = ((const float*)&na0)[c];
                As[nbuf][gk + c][gr + 64] = ((const float*)&na1)[c];
                Bs[nbuf][gk + c][gr]      = ((const float*)&nb0)[c];
                Bs[nbuf][gk + c][gr + 64] = ((const float*)&nb1)[c];
            }
        }
        __syncthreads();
    }

    // epilogue: + bias, store Y (per m-pair: two STG.128 rows of 4 cols)
    const float4 bi = *(const float4*)(bias + bn + tn0);
#pragma unroll
    for (int p = 0; p < 8; p++) {
        float r0c0, r1c0, r0c1, r1c1, r0c2, r1c2, r0c3, r1c3;
        unpack2(acc[p][0], r0c0, r1c0);
        unpack2(acc[p][1], r0c1, r1c1);
        unpack2(acc[p][2], r0c2, r1c2);
        unpack2(acc[p][3], r0c3, r1c3);
        const size_t row0 = (size_t)(bm + tm0 + 2 * p);
        float4 o0 = {r0c0 + bi.x, r0c1 + bi.y, r0c2 + bi.z, r0c3 + bi.w};
        float4 o1 = {r1c0 + bi.x, r1c1 + bi.y, r1c2 + bi.z, r1c3 + bi.w};
        *(float4*)(g_Y + row0 * D_DIM + bn + tn0)       = o0;
        *(float4*)(g_Y + (row0 + 1) * D_DIM + bn + tn0) = o1;
    }
}

// ---------------------------------------------------------------------------
// Fused fwd+bwd LIF scan, time-chunked with warm-up (verified exact).
// ---------------------------------------------------------------------------
#define L_CH  256
#define W_UP  96
#define NCH   (T_DIM / L_CH)
#define UNR   16

__device__ __forceinline__ void lif_step(float& v, float c, bool& s) {
    v = v + (c - v) * 0.5f;
    s = (v >= 1.0f);
    v = s ? 0.0f : v;
}

__global__ void scan_kernel(float* __restrict__ out) {
    const int l  = blockIdx.x * blockDim.x + threadIdx.x;
    const int t0 = blockIdx.y * L_CH;
    unsigned fb[L_CH / 32];

    float v = 0.0f;
    {
        const int tb = (t0 - W_UP < 0) ? 0 : (t0 - W_UP);
        for (int tw = tb; tw < t0; tw += UNR) {
            float c[UNR];
#pragma unroll
            for (int i = 0; i < UNR; i++) c[i] = g_Y[(size_t)(tw + i) * BD + l];
#pragma unroll
            for (int i = 0; i < UNR; i++) { bool s; lif_step(v, c[i], s); }
        }
#pragma unroll
        for (int w = 0; w < L_CH / 32; w++) {
            unsigned bits = 0;
#pragma unroll 1
            for (int h = 0; h < 2; h++) {
                float c[UNR];
#pragma unroll
                for (int i = 0; i < UNR; i++)
                    c[i] = g_Y[(size_t)(t0 + w * 32 + h * UNR + i) * BD + l];
#pragma unroll
                for (int i = 0; i < UNR; i++) {
                    bool s; lif_step(v, c[i], s);
                    bits |= (unsigned)s << (h * UNR + i);
                }
            }
            fb[w] = bits;
        }
    }

    v = 0.0f;
    {
        const int te = (t0 + L_CH + W_UP > T_DIM) ? T_DIM : (t0 + L_CH + W_UP);
        for (int tw = te; tw > t0 + L_CH; tw -= UNR) {
            float c[UNR];
#pragma unroll
            for (int i = 0; i < UNR; i++) c[i] = g_Y[(size_t)(tw - 1 - i) * BD + l];
#pragma unroll
            for (int i = 0; i < UNR; i++) { bool s; lif_step(v, c[i], s); }
        }
#pragma unroll
        for (int w = L_CH / 32 - 1; w >= 0; w--) {
            const unsigned bits = fb[w];
#pragma unroll 1
            for (int h = 1; h >= 0; h--) {
                float c[UNR];
#pragma unroll
                for (int i = 0; i < UNR; i++)
                    c[i] = g_Y[(size_t)(t0 + w * 32 + h * UNR + (UNR - 1) - i) * BD + l];
#pragma unroll
                for (int i = 0; i < UNR; i++) {
                    const int ti = h * UNR + (UNR - 1) - i;
                    bool s; lif_step(v, c[i], s);
                    out[(size_t)(t0 + w * 32 + ti) * BD + l] =
                        (s ? 1.0f : 0.0f) + (float)((bits >> ti) & 1u);
                }
            }
        }
    }
}

// ---------------------------------------------------------------------------
extern "C" void kernel_launch(void* const* d_in, const int* in_sizes, int n_in,
                              void* d_out, int out_size) {
    const float* x = (const float*)d_in[0];
    const float* W = (const float*)d_in[1];
    const float* b = (const float*)d_in[2];
    float* out = (float*)d_out;

    dim3 ggrid(D_DIM / BNT, M_DIM / BMT);   // (4, 512): n inner -> X L2 reuse
    sgemm_kernel<<<ggrid, 256>>>(x, W, b);

    dim3 sgrid(BD / 256, NCH);              // (64, 8)
    scan_kernel<<<sgrid, 256>>>(out);
}